// round 16
// baseline (speedup 1.0000x reference)
#include <cuda_runtime.h>

#define BB 64
#define SS 512
#define EE 128
#define TT 10
#define ROWS (BB*SS)

#define NPRE 24
#define NREC 128          // 2 chains per batch
#define NBLK (NPRE + NREC)
#define NCHUNK 8          // 8 chunks x 64 steps
#define NBLKS 84          // 336 steps per chain = 84 x 4
#define S0_B 176          // chain B start (160-step warmup, publishes >= 336)

// scratch (static device globals: allocation-free, zero-initialized at load)
__device__ float g_pre[ROWS * 16 + 128];  // [row][w*4+g] (+ pad for prefetch overshoot)
__device__ int g_cnt[NCHUNK];             // pre chunk counters (monotone across runs)
__device__ int g_eb[NREC];                // rec per-block epochs

__device__ __forceinline__ float tanh_approx(float x) {
    float y;
    asm("tanh.approx.f32 %0, %1;" : "=f"(y) : "f"(x));
    return y;
}

// acquire load: plain L2 read, no atomic-ALU serialization
__device__ __forceinline__ int ld_acquire(const int* p) {
    int v;
    asm volatile("ld.acquire.gpu.global.b32 %0, [%1];" : "=r"(v) : "l"(p) : "memory");
    return v;
}

__constant__ int C_ORDER[NCHUNK] = {0, 2, 3, 1, 4, 5, 6, 7};  // chunk production order

// ---------------------------------------------------------------------------
// One fused kernel, 152 blocks = one per SM on GB300.
//   [0,24)    pre : produces chunks in order {0,2,3,1,4,5,6,7}; block bid
//                   handles s-offsets {bid, bid+24, bid+48} of each chunk.
//   [24,152)  rec : 2 chains per batch. r = bid-24; batch = r>>1, half = r&1.
//                   half 0: steps 0..335 (publish all);
//                   half 1: steps 176..511 (160-step warmup, publish >= 336).
//                   warp 0 lanes 0-15 = recurrence; warp 1 lanes 0-15 = out.
// Contraction (f = sigmoid(q), |q|<=1 -> f<=0.731) makes the warmup converge
// to the true state to ~1e-15 before any published step.
// ---------------------------------------------------------------------------
__global__ void __launch_bounds__(256, 1) fused_kernel(
    const int* __restrict__ x, const float* __restrict__ emb,
    const float* __restrict__ Wf, const float* __restrict__ bf, const float* __restrict__ thf,
    const float* __restrict__ Wi, const float* __restrict__ bi, const float* __restrict__ thi,
    const float* __restrict__ Wu, const float* __restrict__ bu, const float* __restrict__ thu,
    const float* __restrict__ Wo, const float* __restrict__ bo, const float* __restrict__ tho,
    const float* __restrict__ Wt, const float* __restrict__ bt,
    float* __restrict__ out)
{
    const unsigned HMASK = 0xFFFFu;
    int bid = blockIdx.x;
    int tid = threadIdx.x;

    __shared__ float4 sW4[EE * 4];     // pre weights
    __shared__ float4 sC4[4];          // pre bias+theta
    __shared__ float4 sH4[SS];         // rec->out hidden states (local step index)
    __shared__ float  sWt[4 * TT];
    __shared__ float  sbt[TT];
    __shared__ volatile int sFlag;     // published 16-step groups

    if (bid < NPRE) {
        // ================= PRE =================
        for (int idx = tid; idx < EE * 4; idx += 256) {
            int k = idx >> 2, w = idx & 3;
            sW4[idx] = make_float4(Wf[k * 4 + w], Wi[k * 4 + w],
                                   Wu[k * 4 + w], Wo[k * 4 + w]);
        }
        if (tid < 4) {
            sC4[tid] = make_float4(bf[tid] + thf[tid], bi[tid] + thi[tid],
                                   bu[tid] + thu[tid], bo[tid] + tho[tid]);
        }
        __syncthreads();

        int w  = tid & 3;
        int bb = tid >> 2;               // batch 0..63
        float4 C = sC4[w];

        for (int ci = 0; ci < NCHUNK; ci++) {
            int ch = C_ORDER[ci];
            for (int so = bid; so < 64; so += NPRE) {
                int s   = ch * 64 + so;
                int row = bb * SS + s;
                const float4* e4 = (const float4*)(emb + (size_t)x[row] * EE);

                float4 A0 = make_float4(0.f, 0.f, 0.f, 0.f);
                float4 A1 = A0, A2 = A0, A3 = A0;
                #pragma unroll
                for (int k4 = 0; k4 < 32; k4++) {
                    float4 e = e4[k4];
                    int k = k4 * 4;
                    float4 w0 = sW4[(k + 0) * 4 + w];
                    float4 w1 = sW4[(k + 1) * 4 + w];
                    float4 w2 = sW4[(k + 2) * 4 + w];
                    float4 w3 = sW4[(k + 3) * 4 + w];
                    A0.x = fmaf(e.x, w0.x, A0.x); A0.y = fmaf(e.x, w0.y, A0.y);
                    A0.z = fmaf(e.x, w0.z, A0.z); A0.w = fmaf(e.x, w0.w, A0.w);
                    A1.x = fmaf(e.y, w1.x, A1.x); A1.y = fmaf(e.y, w1.y, A1.y);
                    A1.z = fmaf(e.y, w1.z, A1.z); A1.w = fmaf(e.y, w1.w, A1.w);
                    A2.x = fmaf(e.z, w2.x, A2.x); A2.y = fmaf(e.z, w2.y, A2.y);
                    A2.z = fmaf(e.z, w2.z, A2.z); A2.w = fmaf(e.z, w2.w, A2.w);
                    A3.x = fmaf(e.w, w3.x, A3.x); A3.y = fmaf(e.w, w3.y, A3.y);
                    A3.z = fmaf(e.w, w3.z, A3.z); A3.w = fmaf(e.w, w3.w, A3.w);
                }
                float4 r;
                r.x = (A0.x + A1.x) + (A2.x + A3.x) + C.x;
                r.y = (A0.y + A1.y) + (A2.y + A3.y) + C.y;
                r.z = (A0.z + A1.z) + (A2.z + A3.z) + C.z;
                r.w = (A0.w + A1.w) + (A2.w + A3.w) + C.w;
                ((float4*)g_pre)[(size_t)row * 4 + w] = r;
            }
            __threadfence();
            __syncthreads();
            if (tid == 0) atomicAdd(&g_cnt[ch], 1);
            __syncthreads();
        }
    } else {
        // ================= REC (warp 0) + OUT (warp 1) =================
        int r    = bid - NPRE;
        int b    = r >> 1;
        int half = r & 1;
        const int s0      = half ? S0_B : 0;
        const int pphase  = half ? 3 : 15;    // poll blks: (blk&15)==pphase
        const int pubmin  = half ? 43 : 3;    // first publishing blk
        const int pubsub  = half ? 10 : 0;    // group-index offset
        const int ngrp    = half ? 11 : 21;   // published 16-row groups
        const int lbase   = half ? 160 : 0;   // local idx of first published row
        const int sbase   = half ? 336 : 0;   // global s of first published row

        if (tid == 0) sFlag = 0;
        __syncthreads();

        if (tid < 32) {
            // ---- warp 0: pure recurrence on lanes 0-15 ----
            if (tid >= 16) return;
            int lane = tid;

            int e = 0;
            if (lane == 0) e = atomicAdd(&g_eb[r], 1) + 1;
            e = __shfl_sync(HMASK, e, 0);
            const int need = NPRE * e;

            int g = lane >> 2;
            int w = lane & 3;

            const float* Wg = (g == 0) ? Wf : (g == 1) ? Wi : (g == 2) ? Wu : Wo;
            float Wh0 = Wg[(128 + 0) * 4 + w];
            float Wh1 = Wg[(128 + 1) * 4 + w];
            float Wh2 = Wg[(128 + 2) * 4 + w];
            float Wh3 = Wg[(128 + 3) * 4 + w];

            const bool m0 = (w != 0);
            const bool m2 = (w == 0) | (w >= 2);
            const bool m3 = (w == 0) | (w == 3);
            const float tsc = (g == 2) ? 1.0f : 0.5f;
            const int gbase = lane & 12;

            const float* P = g_pre + ((size_t)b * SS + s0) * 16 + (w * 4 + g);
            float* sH = (float*)sH4;

            float hv = 0.f, cx = 0.f;

            // wait for the chunk containing s0
            {
                int ic = s0 >> 6;
                while (ld_acquire(&g_cnt[ic]) < need) __nanosleep(64);
            }
            __syncwarp(HMASK);

            float pb0 = P[0 * 16], pb1 = P[1 * 16], pb2 = P[2 * 16], pb3 = P[3 * 16];

            for (int blk = 0; blk < NBLKS; blk++) {
                float pc0 = pb0, pc1 = pb1, pc2 = pb2, pc3 = pb3;

                // gate prefetch on the next chunk boundary
                if ((blk & 15) == pphase) {
                    int ch = (s0 + 4 * blk + 11) >> 6;
                    if (ch > 7) ch = 7;
                    while (ld_acquire(&g_cnt[ch]) < need) __nanosleep(128);
                    __syncwarp(HMASK);
                }

                pb0 = P[4 * 16]; pb1 = P[5 * 16]; pb2 = P[6 * 16]; pb3 = P[7 * 16];
                P += 64;

                #pragma unroll
                for (int k = 0; k < 4; k++) {
                    float p = (k == 0) ? pc0 : (k == 1) ? pc1 : (k == 2) ? pc2 : pc3;

                    float hx0 = __shfl_sync(HMASK, hv, 0, 16);
                    float hx1 = __shfl_sync(HMASK, hv, 1, 16);
                    float hx2 = __shfl_sync(HMASK, hv, 2, 16);
                    float hx3 = __shfl_sync(HMASK, hv, 3, 16);

                    float a = fmaf(hx3, Wh3,
                               fmaf(hx2, Wh2,
                                 fmaf(hx1, Wh1,
                                   fmaf(hx0, Wh0, p))));
                    float z = __cosf(a);

                    float z0 = __shfl_sync(HMASK, z, gbase | 0, 16);
                    float z1 = __shfl_sync(HMASK, z, gbase | 1, 16);
                    float z2 = __shfl_sync(HMASK, z, gbase | 2, 16);
                    float z3 = __shfl_sync(HMASK, z, gbase | 3, 16);

                    float q = (m0 ? z0 : 1.0f) * z1;
                    q = q * (m2 ? z2 : 1.0f);
                    q = q * (m3 ? z3 : 1.0f);

                    float t = tanh_approx(q * tsc);

                    float ti = __shfl_sync(HMASK, t, 4  | w, 16);
                    float tu = __shfl_sync(HMASK, t, 8  | w, 16);
                    float to = __shfl_sync(HMASK, t, 12 | w, 16);

                    float fv = fmaf(t,  0.5f, 0.5f);
                    float iv = fmaf(ti, 0.5f, 0.5f);
                    float ov = fmaf(to, 0.5f, 0.5f);
                    float c  = fmaf(fv, cx, iv * tu);
                    float hn = ov * tanh_approx(c);

                    cx = c;
                    hv = hn;
                    if (g == 0) sH[(blk * 4 + k) * 4 + w] = hn;
                }

                // publish completed 16-step group to the consumer warp
                if ((blk & 3) == 3 && blk >= pubmin) {
                    __threadfence_block();
                    __syncwarp(HMASK);
                    if (lane == 0) sFlag = ((blk + 1) >> 2) - pubsub;
                }
            }
        } else if (tid < 64) {
            // ---- warp 1: logits + log_softmax consumer (lanes 0-15) ----
            int l = tid - 32;
            for (int idx = l; idx < 4 * TT; idx += 32) sWt[idx] = Wt[idx];
            for (int idx = l; idx < TT; idx += 32) sbt[idx] = bt[idx];
            __syncwarp();
            if (l >= 16) return;

            float* outb = out + (size_t)b * SS * TT;

            for (int grp = 0; grp < ngrp; grp++) {
                while (sFlag < grp + 1) __nanosleep(192);
                __threadfence_block();

                int loc = lbase + grp * 16 + l;   // sH index
                int s   = sbase + grp * 16 + l;   // output row
                float4 h = sH4[loc];

                float lg[TT];
                #pragma unroll
                for (int t = 0; t < TT; t++) {
                    float v = sbt[t];
                    v = fmaf(h.x, sWt[0 * TT + t], v);
                    v = fmaf(h.y, sWt[1 * TT + t], v);
                    v = fmaf(h.z, sWt[2 * TT + t], v);
                    v = fmaf(h.w, sWt[3 * TT + t], v);
                    lg[t] = v;
                }
                float mx = lg[0];
                #pragma unroll
                for (int t = 1; t < TT; t++) mx = fmaxf(mx, lg[t]);
                float sum = 0.f;
                #pragma unroll
                for (int t = 0; t < TT; t++) sum += __expf(lg[t] - mx);
                float lse = mx + __logf(sum);

                float2* o2 = (float2*)(outb + (size_t)s * TT);
                #pragma unroll
                for (int t = 0; t < TT; t += 2)
                    o2[t >> 1] = make_float2(lg[t] - lse, lg[t + 1] - lse);
            }
        }
        // warps 2-7: retire
    }
}

// ---------------------------------------------------------------------------
extern "C" void kernel_launch(void* const* d_in, const int* in_sizes, int n_in,
                              void* d_out, int out_size)
{
    (void)in_sizes; (void)n_in; (void)out_size;
    const int*   x   = (const int*)  d_in[0];
    const float* emb = (const float*)d_in[1];
    const float* Wf  = (const float*)d_in[2];
    const float* bf  = (const float*)d_in[3];
    const float* thf = (const float*)d_in[4];
    const float* Wi  = (const float*)d_in[5];
    const float* bi  = (const float*)d_in[6];
    const float* thi = (const float*)d_in[7];
    const float* Wu  = (const float*)d_in[8];
    const float* bu  = (const float*)d_in[9];
    const float* thu = (const float*)d_in[10];
    const float* Wo  = (const float*)d_in[11];
    const float* bo  = (const float*)d_in[12];
    const float* tho = (const float*)d_in[13];
    const float* Wt  = (const float*)d_in[14];
    const float* bt  = (const float*)d_in[15];
    float* out = (float*)d_out;

    fused_kernel<<<NBLK, 256>>>(x, emb, Wf, bf, thf, Wi, bi, thi,
                                Wu, bu, thu, Wo, bo, tho, Wt, bt, out);
}

// round 17
// speedup vs baseline: 2.8507x; 2.8507x over previous
#include <cuda_runtime.h>

#define BB 64
#define SS 512
#define EE 128
#define TT 10
#define ROWS (BB*SS)

#define NPRE 64
#define NREC 64           // one block per batch; chains A+B on separate warps
#define NBLK (NPRE + NREC)
#define NCHUNK 8          // 8 chunks x 64 steps
#define NBLKS 84          // 336 steps per chain = 84 x 4
#define S0_B 176          // chain B start (160-step warmup, publishes >= 336)

// scratch (static device globals: allocation-free, zero-initialized at load)
__device__ float g_pre[ROWS * 16 + 128];  // [row][w*4+g] (+ pad for prefetch overshoot)
__device__ int g_cnt[NCHUNK];             // pre chunk counters (monotone across runs)
__device__ int g_eb[NREC];                // rec per-block epochs

__device__ __forceinline__ float tanh_approx(float x) {
    float y;
    asm("tanh.approx.f32 %0, %1;" : "=f"(y) : "f"(x));
    return y;
}

// acquire load: plain L2 read, no atomic-ALU serialization
__device__ __forceinline__ int ld_acquire(const int* p) {
    int v;
    asm volatile("ld.acquire.gpu.global.b32 %0, [%1];" : "=r"(v) : "l"(p) : "memory");
    return v;
}

// ---------------------------------------------------------------------------
// One fused kernel, 128 blocks <= 152 SMs (all wave-1, no co-residency).
//   [0,64)   pre : chunk c = steps [64c, 64c+64); block bid produces step
//                  s = 64c + bid of every batch (R15's proven 145-reg shape);
//                  publishes g_cnt[c].
//   [64,128) rec : block = one batch. warp 0 = chain A (steps 0..335),
//                  warp 1 = chain B (steps 176..511; 160-step warmup,
//                  publishes >= 336) — separate SMSPs, no issue contention.
//                  warps 2/3 = per-chain logits+log_softmax consumers.
// Contraction (f = sigmoid(q), |q|<=1 -> f<=0.731) makes the warmup converge
// far below the 1e-3 threshold (verified: rel_err identical to 1-chain run).
// Monotone epoch counters on g_cnt make the protocol graph-replay-safe.
// ---------------------------------------------------------------------------
__global__ void __launch_bounds__(256, 1) fused_kernel(
    const int* __restrict__ x, const float* __restrict__ emb,
    const float* __restrict__ Wf, const float* __restrict__ bf, const float* __restrict__ thf,
    const float* __restrict__ Wi, const float* __restrict__ bi, const float* __restrict__ thi,
    const float* __restrict__ Wu, const float* __restrict__ bu, const float* __restrict__ thu,
    const float* __restrict__ Wo, const float* __restrict__ bo, const float* __restrict__ tho,
    const float* __restrict__ Wt, const float* __restrict__ bt,
    float* __restrict__ out)
{
    const unsigned HMASK = 0xFFFFu;
    int bid = blockIdx.x;
    int tid = threadIdx.x;

    __shared__ float4 sW4[EE * 4];     // pre weights
    __shared__ float4 sC4[4];          // pre bias+theta
    __shared__ float4 sHA4[336];       // chain A hidden states (local step idx)
    __shared__ float4 sHB4[176];       // chain B published states (local-160)
    __shared__ float  sWt[4 * TT];
    __shared__ float  sbt[TT];
    __shared__ volatile int sFlagA;    // A: published 16-step groups
    __shared__ volatile int sFlagB;    // B: published 16-step groups
    __shared__ int sE;

    if (bid < NPRE) {
        // ================= PRE (identical to the proven R15 shape) =================
        for (int idx = tid; idx < EE * 4; idx += 256) {
            int k = idx >> 2, w = idx & 3;
            sW4[idx] = make_float4(Wf[k * 4 + w], Wi[k * 4 + w],
                                   Wu[k * 4 + w], Wo[k * 4 + w]);
        }
        if (tid < 4) {
            sC4[tid] = make_float4(bf[tid] + thf[tid], bi[tid] + thi[tid],
                                   bu[tid] + thu[tid], bo[tid] + tho[tid]);
        }
        __syncthreads();

        int w  = tid & 3;
        int bb = tid >> 2;               // batch 0..63
        float4 C = sC4[w];

        for (int c = 0; c < NCHUNK; c++) {
            int s   = c * 64 + bid;      // bid < 64
            int row = bb * SS + s;
            const float4* e4 = (const float4*)(emb + (size_t)x[row] * EE);

            float4 A0 = make_float4(0.f, 0.f, 0.f, 0.f);
            float4 A1 = A0, A2 = A0, A3 = A0;
            #pragma unroll
            for (int k4 = 0; k4 < 32; k4++) {
                float4 e = e4[k4];
                int k = k4 * 4;
                float4 w0 = sW4[(k + 0) * 4 + w];
                float4 w1 = sW4[(k + 1) * 4 + w];
                float4 w2 = sW4[(k + 2) * 4 + w];
                float4 w3 = sW4[(k + 3) * 4 + w];
                A0.x = fmaf(e.x, w0.x, A0.x); A0.y = fmaf(e.x, w0.y, A0.y);
                A0.z = fmaf(e.x, w0.z, A0.z); A0.w = fmaf(e.x, w0.w, A0.w);
                A1.x = fmaf(e.y, w1.x, A1.x); A1.y = fmaf(e.y, w1.y, A1.y);
                A1.z = fmaf(e.y, w1.z, A1.z); A1.w = fmaf(e.y, w1.w, A1.w);
                A2.x = fmaf(e.z, w2.x, A2.x); A2.y = fmaf(e.z, w2.y, A2.y);
                A2.z = fmaf(e.z, w2.z, A2.z); A2.w = fmaf(e.z, w2.w, A2.w);
                A3.x = fmaf(e.w, w3.x, A3.x); A3.y = fmaf(e.w, w3.y, A3.y);
                A3.z = fmaf(e.w, w3.z, A3.z); A3.w = fmaf(e.w, w3.w, A3.w);
            }
            float4 r;
            r.x = (A0.x + A1.x) + (A2.x + A3.x) + C.x;
            r.y = (A0.y + A1.y) + (A2.y + A3.y) + C.y;
            r.z = (A0.z + A1.z) + (A2.z + A3.z) + C.z;
            r.w = (A0.w + A1.w) + (A2.w + A3.w) + C.w;
            ((float4*)g_pre)[(size_t)row * 4 + w] = r;

            __threadfence();
            __syncthreads();
            if (tid == 0) atomicAdd(&g_cnt[c], 1);
            __syncthreads();
        }
    } else {
        // ================= REC (warps 0,1) + OUT (warps 2,3) =================
        int b = bid - NPRE;

        if (tid == 0) {
            sFlagA = 0;
            sFlagB = 0;
            sE = atomicAdd(&g_eb[b], 1) + 1;
        }
        __syncthreads();
        const int need = NPRE * sE;

        int wid  = tid >> 5;
        int lane = tid & 31;

        if (wid < 2) {
            // ---- recurrence warp: wid 0 = chain A, wid 1 = chain B ----
            if (lane >= 16) return;
            const int half   = wid;
            const int s0     = half ? S0_B : 0;
            const int pphase = half ? 3 : 15;    // poll at (blk&15)==pphase
            const int pubmin = half ? 43 : 3;    // first publishing blk
            const int pubsub = half ? 10 : 0;    // group-index offset
            const int lbase  = half ? 160 : 0;   // first stored local step

            int g = lane >> 2;
            int w = lane & 3;

            const float* Wg = (g == 0) ? Wf : (g == 1) ? Wi : (g == 2) ? Wu : Wo;
            float Wh0 = Wg[(128 + 0) * 4 + w];
            float Wh1 = Wg[(128 + 1) * 4 + w];
            float Wh2 = Wg[(128 + 2) * 4 + w];
            float Wh3 = Wg[(128 + 3) * 4 + w];

            const bool m0 = (w != 0);
            const bool m2 = (w == 0) | (w >= 2);
            const bool m3 = (w == 0) | (w == 3);
            const float tsc = (g == 2) ? 1.0f : 0.5f;
            const int gbase = lane & 12;

            const float* P = g_pre + ((size_t)b * SS + s0) * 16 + (w * 4 + g);
            float* sH = half ? (float*)sHB4 : (float*)sHA4;
            volatile int* flag = half ? &sFlagB : &sFlagA;

            float hv = 0.f, cx = 0.f;

            // wait for the chunk containing s0
            {
                int ic = s0 >> 6;
                while (ld_acquire(&g_cnt[ic]) < need) __nanosleep(64);
            }
            __syncwarp(HMASK);

            float pb0 = P[0 * 16], pb1 = P[1 * 16], pb2 = P[2 * 16], pb3 = P[3 * 16];

            for (int blk = 0; blk < NBLKS; blk++) {
                float pc0 = pb0, pc1 = pb1, pc2 = pb2, pc3 = pb3;

                // gate prefetch on the next chunk boundary
                if ((blk & 15) == pphase) {
                    int ch = (s0 + 4 * blk + 11) >> 6;
                    if (ch > 7) ch = 7;
                    while (ld_acquire(&g_cnt[ch]) < need) __nanosleep(128);
                    __syncwarp(HMASK);
                }

                pb0 = P[4 * 16]; pb1 = P[5 * 16]; pb2 = P[6 * 16]; pb3 = P[7 * 16];
                P += 64;

                #pragma unroll
                for (int k = 0; k < 4; k++) {
                    float p = (k == 0) ? pc0 : (k == 1) ? pc1 : (k == 2) ? pc2 : pc3;

                    float hx0 = __shfl_sync(HMASK, hv, 0, 16);
                    float hx1 = __shfl_sync(HMASK, hv, 1, 16);
                    float hx2 = __shfl_sync(HMASK, hv, 2, 16);
                    float hx3 = __shfl_sync(HMASK, hv, 3, 16);

                    float a = fmaf(hx3, Wh3,
                               fmaf(hx2, Wh2,
                                 fmaf(hx1, Wh1,
                                   fmaf(hx0, Wh0, p))));
                    float z = __cosf(a);

                    float z0 = __shfl_sync(HMASK, z, gbase | 0, 16);
                    float z1 = __shfl_sync(HMASK, z, gbase | 1, 16);
                    float z2 = __shfl_sync(HMASK, z, gbase | 2, 16);
                    float z3 = __shfl_sync(HMASK, z, gbase | 3, 16);

                    float q = (m0 ? z0 : 1.0f) * z1;
                    q = q * (m2 ? z2 : 1.0f);
                    q = q * (m3 ? z3 : 1.0f);

                    float t = tanh_approx(q * tsc);

                    float ti = __shfl_sync(HMASK, t, 4  | w, 16);
                    float tu = __shfl_sync(HMASK, t, 8  | w, 16);
                    float to = __shfl_sync(HMASK, t, 12 | w, 16);

                    float fv = fmaf(t,  0.5f, 0.5f);
                    float iv = fmaf(ti, 0.5f, 0.5f);
                    float ov = fmaf(to, 0.5f, 0.5f);
                    float c  = fmaf(fv, cx, iv * tu);
                    float hn = ov * tanh_approx(c);

                    cx = c;
                    hv = hn;
                    int ls = blk * 4 + k;
                    if (g == 0 && ls >= lbase) sH[(ls - lbase) * 4 + w] = hn;
                }

                // publish completed 16-step group to this chain's consumer
                if ((blk & 3) == 3 && blk >= pubmin) {
                    __threadfence_block();
                    __syncwarp(HMASK);
                    if (lane == 0) *flag = ((blk + 1) >> 2) - pubsub;
                }
            }
        } else if (wid < 4) {
            // ---- consumer warp: wid 2 = chain A, wid 3 = chain B ----
            const int half = wid - 2;
            for (int idx = lane; idx < 4 * TT; idx += 32) sWt[idx] = Wt[idx];
            for (int idx = lane; idx < TT; idx += 32) sbt[idx] = bt[idx];
            __syncwarp();
            if (lane >= 16) return;
            int l = lane;

            const int ngrp  = half ? 11 : 21;
            const int sbase = half ? 336 : 0;
            volatile int* flag = half ? &sFlagB : &sFlagA;
            const float4* sHp = half ? sHB4 : sHA4;

            float* outb = out + (size_t)b * SS * TT;

            for (int grp = 0; grp < ngrp; grp++) {
                while (*flag < grp + 1) __nanosleep(192);
                __threadfence_block();

                int s = sbase + grp * 16 + l;
                float4 h = sHp[grp * 16 + l];

                float lg[TT];
                #pragma unroll
                for (int t = 0; t < TT; t++) {
                    float v = sbt[t];
                    v = fmaf(h.x, sWt[0 * TT + t], v);
                    v = fmaf(h.y, sWt[1 * TT + t], v);
                    v = fmaf(h.z, sWt[2 * TT + t], v);
                    v = fmaf(h.w, sWt[3 * TT + t], v);
                    lg[t] = v;
                }
                float mx = lg[0];
                #pragma unroll
                for (int t = 1; t < TT; t++) mx = fmaxf(mx, lg[t]);
                float sum = 0.f;
                #pragma unroll
                for (int t = 0; t < TT; t++) sum += __expf(lg[t] - mx);
                float lse = mx + __logf(sum);

                float2* o2 = (float2*)(outb + (size_t)s * TT);
                #pragma unroll
                for (int t = 0; t < TT; t += 2)
                    o2[t >> 1] = make_float2(lg[t] - lse, lg[t + 1] - lse);
            }
        }
        // warps 4-7: retire after init
    }
}

// ---------------------------------------------------------------------------
extern "C" void kernel_launch(void* const* d_in, const int* in_sizes, int n_in,
                              void* d_out, int out_size)
{
    (void)in_sizes; (void)n_in; (void)out_size;
    const int*   x   = (const int*)  d_in[0];
    const float* emb = (const float*)d_in[1];
    const float* Wf  = (const float*)d_in[2];
    const float* bf  = (const float*)d_in[3];
    const float* thf = (const float*)d_in[4];
    const float* Wi  = (const float*)d_in[5];
    const float* bi  = (const float*)d_in[6];
    const float* thi = (const float*)d_in[7];
    const float* Wu  = (const float*)d_in[8];
    const float* bu  = (const float*)d_in[9];
    const float* thu = (const float*)d_in[10];
    const float* Wo  = (const float*)d_in[11];
    const float* bo  = (const float*)d_in[12];
    const float* tho = (const float*)d_in[13];
    const float* Wt  = (const float*)d_in[14];
    const float* bt  = (const float*)d_in[15];
    float* out = (float*)d_out;

    fused_kernel<<<NBLK, 256>>>(x, emb, Wf, bf, thf, Wi, bi, thi,
                                Wu, bu, thu, Wo, bo, tho, Wt, bt, out);
}